// round 1
// baseline (speedup 1.0000x reference)
#include <cuda_runtime.h>

typedef unsigned long long ull;

// ---- f32x2 packed helpers (Blackwell sm_103a) ----
__device__ __forceinline__ ull pk(float lo, float hi) {
    ull r;
    asm("mov.b64 %0, {%1,%2};" : "=l"(r)
        : "r"(__float_as_uint(lo)), "r"(__float_as_uint(hi)));
    return r;
}
__device__ __forceinline__ void upk(ull v, float& lo, float& hi) {
    unsigned a, b;
    asm("mov.b64 {%0,%1}, %2;" : "=r"(a), "=r"(b) : "l"(v));
    lo = __uint_as_float(a);
    hi = __uint_as_float(b);
}
__device__ __forceinline__ ull fma2(ull a, ull b, ull c) {
    ull d;
    asm("fma.rn.f32x2 %0, %1, %2, %3;" : "=l"(d) : "l"(a), "l"(b), "l"(c));
    return d;
}

#define H   128   // hidden dim
#define HP  64    // h-pairs
#define TPB 128   // threads per block
#define PPT 4     // points per thread

__global__ __launch_bounds__(TPB)
void cubeflow_fused_kernel(const float* __restrict__ input,
                           const float* __restrict__ latent,
                           const float* __restrict__ W1,
                           const float* __restrict__ b1,
                           const float* __restrict__ W2,
                           const float* __restrict__ b2,
                           float* __restrict__ out,
                           int P, int BP)
{
    // Weights pre-interleaved as (even-h, odd-h) pairs so the inner loop
    // needs zero pack MOVs: LDS.128 naturally yields aligned reg pairs.
    __shared__ float4 sW01[HP];  // (w0e, w0o, w1e, w1o)
    __shared__ float4 sW23[HP];  // (w2e, w2o, w3e, w3o)
    __shared__ float4 sBB [HP];  // (b1e, b1o, w20e, w20o)
    __shared__ float2 sW21[HP];  // (w21e, w21o)

    const int tid = threadIdx.x;
    if (tid < HP) {
        const int h0 = 2 * tid, h1 = h0 + 1;
        float4 r0 = reinterpret_cast<const float4*>(W1)[h0];
        float4 r1 = reinterpret_cast<const float4*>(W1)[h1];
        sW01[tid] = make_float4(r0.x, r1.x, r0.y, r1.y);
        sW23[tid] = make_float4(r0.z, r1.z, r0.w, r1.w);
        sBB [tid] = make_float4(b1[h0], b1[h1], W2[h0], W2[h1]);
        sW21[tid] = make_float2(W2[H + h0], W2[H + h1]);
    }
    __syncthreads();

    const int unit = blockIdx.x * TPB + tid;       // one unit = 4 points
    const int p0   = unit * PPT;
    if (p0 >= BP) return;

    const int   bidx  = p0 / P;                    // batch index
    const float theta = latent[bidx] * 10.0f;
    float sn, cs;
    sincosf(theta, &sn, &cs);

    // 4 points * 3 coords = 12 floats = 3 coalesced float4 loads
    const float4* in4 = reinterpret_cast<const float4*>(input) + (size_t)unit * 3;
    const float4 q0 = in4[0], q1 = in4[1], q2 = in4[2];
    float x0[PPT] = { q0.x, q0.w, q1.z, q2.y };
    float x1[PPT] = { q0.y, q1.x, q1.w, q2.z };
    float x2[PPT] = { q0.z, q1.y, q2.x, q2.w };

    // ---- cubeflow (z-rotation closed form) + eval/con stores ----
    float ev[PPT];
    #pragma unroll
    for (int k = 0; k < PPT; ++k) {
        const float d0 = x0[k] - theta, d1 = x1[k], d2 = x2[k];
        const float f1 = 1.4f * (d0 * d0) + 1.4f * (d1 * d1)
                       + 0.2f * (d2 * d2) - 0.5f;
        const float a2  = d2 + 0.4f;
        const float c20 = d0 * cs + d1 * sn;
        const float c21 = d1 * cs - d0 * sn;
        const float f2v = 3.8f * c20 * c20 + 0.6f * c21 * c21
                        + 3.8f * a2 * a2 - 0.5f;
        const float a3  = d2 - 0.6f;
        const float c30 = d0 * cs - d1 * sn;
        const float c31 = d0 * sn + d1 * cs;
        const float f3v = 0.35f * c30 * c30 + 2.8f * c31 * c31
                        + 2.8f * a3 * a3 - 0.5f;
        ev[k] = fminf(f1, fminf(f2v, f3v));
    }
    *reinterpret_cast<float4*>(out + p0) = make_float4(ev[0], ev[1], ev[2], ev[3]);

    float4* conp = reinterpret_cast<float4*>(out + BP) + p0;   // con: float4/point
    #pragma unroll
    for (int k = 0; k < PPT; ++k)
        conp[k] = make_float4(x0[k], x1[k], x2[k], theta);

    // ---- MLP: h packed in (even,odd) f32x2 pairs ----
    ull X0[PPT], X1[PPT], X2[PPT], A0[PPT], A1[PPT];
    #pragma unroll
    for (int k = 0; k < PPT; ++k) {
        X0[k] = pk(x0[k], x0[k]);
        X1[k] = pk(x1[k], x1[k]);
        X2[k] = pk(x2[k], x2[k]);
        A0[k] = 0ull;  // (0.f, 0.f)
        A1[k] = 0ull;
    }
    const ull TH2 = pk(theta, theta);

    const ulonglong2* u01 = reinterpret_cast<const ulonglong2*>(sW01);
    const ulonglong2* u23 = reinterpret_cast<const ulonglong2*>(sW23);
    const ulonglong2* ubb = reinterpret_cast<const ulonglong2*>(sBB);
    const ull*        u21 = reinterpret_cast<const ull*>(sW21);

    #pragma unroll 4
    for (int hp = 0; hp < HP; ++hp) {
        const ulonglong2 v01 = u01[hp];   // v01.x = w0 pair, v01.y = w1 pair
        const ulonglong2 v23 = u23[hp];   // v23.x = w2 pair, v23.y = w3 pair
        const ulonglong2 vbb = ubb[hp];   // vbb.x = b1 pair, vbb.y = w2out0 pair
        const ull        w21 = u21[hp];   // w2out1 pair
        const ull bias2 = fma2(v23.y, TH2, vbb.x);   // w3*theta + b1 (per h-pair)
        #pragma unroll
        for (int k = 0; k < PPT; ++k) {
            ull t = fma2(v01.x, X0[k],
                    fma2(v01.y, X1[k],
                    fma2(v23.x, X2[k], bias2)));
            float lo, hi;
            upk(t, lo, hi);
            lo = fmaxf(lo, 0.0f);           // relu on ALU pipe
            hi = fmaxf(hi, 0.0f);
            t = pk(lo, hi);
            A0[k] = fma2(vbb.y, t, A0[k]);
            A1[k] = fma2(w21,  t, A1[k]);
        }
    }

    const float b20 = __ldg(b2), b21 = __ldg(b2 + 1);
    float pr[PPT * 2];
    #pragma unroll
    for (int k = 0; k < PPT; ++k) {
        float l, h;
        upk(A0[k], l, h); pr[2 * k + 0] = b20 + l + h;  // fold even+odd partials
        upk(A1[k], l, h); pr[2 * k + 1] = b21 + l + h;
    }
    float4* prp = reinterpret_cast<float4*>(out + (size_t)5 * BP + (size_t)p0 * 2);
    prp[0] = make_float4(pr[0], pr[1], pr[2], pr[3]);
    prp[1] = make_float4(pr[4], pr[5], pr[6], pr[7]);
}

extern "C" void kernel_launch(void* const* d_in, const int* in_sizes, int n_in,
                              void* d_out, int out_size)
{
    const float* input  = (const float*)d_in[0];
    const float* latent = (const float*)d_in[1];
    const float* W1     = (const float*)d_in[2];
    const float* b1     = (const float*)d_in[3];
    const float* W2     = (const float*)d_in[4];
    const float* b2     = (const float*)d_in[5];
    float*       out    = (float*)d_out;

    const int BP = in_sizes[0] / 3;        // total points (B*P)
    const int B  = in_sizes[1];            // latent element count == batch
    const int P  = BP / B;
    const int units  = BP / PPT;
    const int blocks = (units + TPB - 1) / TPB;

    cubeflow_fused_kernel<<<blocks, TPB>>>(input, latent, W1, b1, W2, b2,
                                           out, P, BP);
}